// round 2
// baseline (speedup 1.0000x reference)
#include <cuda_runtime.h>
#include <cstdint>

// RefCondMul: out[t, n] = sum_m x[t, m] * w[inds[t], m, n] + b[inds[t], 0, n]
// Shapes: x [524288, 16] f32, inds [524288] (int64 OR int32 -- detected at
// runtime), w [1024, 16, 16] f32, b [1024, 1, 16] f32, out [524288, 16] f32.
//
// Inputs are identified by element count (all four are distinct), not by
// position, to be robust to harness input ordering.
//
// Layout: one half-warp (16 lanes) per token. Lane n owns output column n.
//  - x:   one coalesced 64B load per token, broadcast via shfl(width=16)
//  - w:   per k, the 16 lanes read one contiguous 64B row -> exactly 1KB/token
//  - out: one coalesced 64B store per token

#define NTOK   524288
#define MDIM   16
#define NDIM   16

__device__ int g_inds_is64;   // 1 if inds buffer is int64, 0 if int32

// Detect inds dtype: view buffer as uint32. For an int64 buffer with values
// in [0,1024), every odd word (high half) is 0. For an int32 buffer the odd
// words are random expert ids; OR over 1024 of them is nonzero w.p. ~1.
__global__ void detect_inds_kernel(const unsigned int* __restrict__ inds32)
{
    __shared__ unsigned int s_or;
    if (threadIdx.x == 0) s_or = 0u;
    __syncthreads();

    unsigned int v = 0u;
    #pragma unroll
    for (int i = 0; i < 4; i++) {
        int idx = threadIdx.x + i * 256;          // covers 1024 "elements"
        v |= inds32[2 * idx + 1];                 // high word if int64
    }
    atomicOr(&s_or, v);
    __syncthreads();

    if (threadIdx.x == 0) g_inds_is64 = (s_or == 0u) ? 1 : 0;
}

__global__ void __launch_bounds__(256) condmul_kernel(
    const float* __restrict__ x,
    const void*  __restrict__ inds_raw,
    const float* __restrict__ w,
    const float* __restrict__ b,
    float* __restrict__ out)
{
    int gid  = blockIdx.x * blockDim.x + threadIdx.x;
    int tok  = gid >> 4;        // token index (half-warp)
    int lane = gid & 15;        // output column within token
    if (tok >= NTOK) return;

    int e;
    if (g_inds_is64) {          // uniform branch across the whole grid
        e = (int)((const long long*)inds_raw)[tok];
    } else {
        e = ((const int*)inds_raw)[tok];
    }

    const float* __restrict__ we = w + (size_t)e * (MDIM * NDIM);

    float xv  = x[tok * MDIM + lane];           // lane holds x[tok, lane]
    float acc = b[e * NDIM + lane];

    #pragma unroll
    for (int k = 0; k < MDIM; k++) {
        // broadcast x[tok, k] within the 16-lane segment
        float xk = __shfl_sync(0xffffffffu, xv, k, 16);
        acc = fmaf(xk, we[k * NDIM + lane], acc);
    }

    out[tok * NDIM + lane] = acc;
}

extern "C" void kernel_launch(void* const* d_in, const int* in_sizes, int n_in,
                              void* d_out, int out_size)
{
    // Identify inputs by element count (all distinct).
    const float* x    = nullptr;
    const void*  inds = nullptr;
    const float* w    = nullptr;
    const float* b    = nullptr;

    for (int i = 0; i < n_in; i++) {
        switch (in_sizes[i]) {
            case NTOK * MDIM:        x    = (const float*)d_in[i]; break; // 8388608
            case NTOK:               inds = d_in[i];               break; // 524288
            case 1024 * MDIM * NDIM: w    = (const float*)d_in[i]; break; // 262144
            case 1024 * NDIM:        b    = (const float*)d_in[i]; break; // 16384
            default: break;
        }
    }

    float* out = (float*)d_out;

    detect_inds_kernel<<<1, 256>>>((const unsigned int*)inds);

    const int threads = 256;
    const int total   = NTOK * 16;              // one thread per (token, col)
    const int blocks  = (total + threads - 1) / threads;
    condmul_kernel<<<blocks, threads>>>(x, inds, w, b, out);
}